// round 4
// baseline (speedup 1.0000x reference)
#include <cuda_runtime.h>
#include <cstdint>

typedef unsigned long long ull;

#define FHW 32
#define NA 9
#define NBOX (FHW*FHW*NA)   // 9216
#define NW 144              // mask words per sorted row (9216/64)
#define CIN 256
#define IMGF 512.0f

// ---------------- scratch ----------------
__device__ float  g_h[1024*512];                 // h[pos][och], 2 MB
__device__ float4 g_boxes[NBOX];
__device__ float  g_scores[NBOX];
__device__ ull    g_keys[NBOX];
__device__ int    g_sidx[NBOX];
__device__ float4 g_sboxes[NBOX];
__device__ ull    g_mask[(size_t)NBOX*NW];       // 10.6 MB
__device__ int    g_keep[NBOX];
__device__ int    g_M;

__constant__ float c_aw[9] = {45.254833995939045f, 32.0f, 22.627416997969522f,
                              90.50966799187809f,  64.0f, 45.254833995939045f,
                              181.01933598375618f, 128.0f, 90.50966799187809f};
__constant__ float c_ah[9] = {22.627416997969522f, 32.0f, 45.254833995939045f,
                              45.254833995939045f, 64.0f, 90.50966799187809f,
                              90.50966799187809f,  128.0f, 181.01933598375618f};

// packed dual-fp32 FMA (Blackwell): acc = a*b + acc, per 32-bit lane
#define FMA2(acc, a, b) asm("fma.rn.f32x2 %0, %1, %2, %0;" : "+l"(acc) : "l"(a), "l"(b))

// ---------------- kernel 1: 3x3 conv 256->512 + bias + relu (f32x2) ----------------
__global__ __launch_bounds__(128) void k_conv(const float* __restrict__ x,
                                              const float* __restrict__ w,
                                              const float* __restrict__ b)
{
    __shared__ ull   xs2[16][18][10];     // [c][col][row], value packed {x,x}
    __shared__ float ws[4896];            // [(c*9+tap)*34 + och], stride 34

    const int tid = threadIdx.x;
    const int sx = blockIdx.x & 1, sy = blockIdx.x >> 1;
    const int x0 = sx * 16, y0 = sy * 8;
    const int ob = blockIdx.y * 32;
    const int pt = tid & 31, ot = tid >> 5;
    const int cg = pt & 3, pr = pt >> 2;
    const int cg4 = cg * 4, ot8 = ot * 8;

    if (blockIdx.x == 0 && blockIdx.y == 0 && tid == 0) g_M = 0;

    ull acc2[4][4];
    #pragma unroll
    for (int o = 0; o < 4; o++)
        #pragma unroll
        for (int i = 0; i < 4; i++) acc2[o][i] = 0ull;

    for (int c0 = 0; c0 < CIN; c0 += 16) {
        __syncthreads();
        for (int t = tid; t < 16*18*10; t += 128) {
            int c = t / 180, r2 = t - c*180, col = r2 / 10, row = r2 - col*10;
            int gx = x0 + col - 1, gy = y0 + row - 1;
            float v = 0.0f;
            if ((unsigned)gx < 32u && (unsigned)gy < 32u)
                v = x[(c0 + c) * 1024 + gy * 32 + gx];
            unsigned xb = __float_as_uint(v);
            ull pv; asm("mov.b64 %0, {%1, %1};" : "=l"(pv) : "r"(xb));
            xs2[c][col][row] = pv;
        }
        {
            int o = 0, rr = tid;
            #pragma unroll 4
            for (int k = 0; k < 36; k++) {
                ws[rr * 34 + o] = w[(size_t)(ob + o) * 2304 + c0 * 9 + rr];
                rr += 128; if (rr >= 144) { rr -= 144; o++; }
            }
        }
        __syncthreads();

        for (int c = 0; c < 16; c++) {
            #pragma unroll
            for (int dy = 0; dy < 3; dy++) {
                ull xv[6];
                #pragma unroll
                for (int q = 0; q < 6; q++) xv[q] = xs2[c][cg4 + q][pr + dy];
                #pragma unroll
                for (int dx = 0; dx < 3; dx++) {
                    const ull* wp = (const ull*)&ws[(c*9 + dy*3 + dx) * 34 + ot8];
                    ull w0 = wp[0], w1 = wp[1], w2v = wp[2], w3v = wp[3];
                    #pragma unroll
                    for (int i = 0; i < 4; i++) {
                        ull xp = xv[i + dx];
                        FMA2(acc2[0][i], w0,  xp);
                        FMA2(acc2[1][i], w1,  xp);
                        FMA2(acc2[2][i], w2v, xp);
                        FMA2(acc2[3][i], w3v, xp);
                    }
                }
            }
        }
    }

    float bias[8];
    #pragma unroll
    for (int o = 0; o < 8; o++) bias[o] = b[ob + ot8 + o];

    const int px = x0 + cg4, py = y0 + pr;
    #pragma unroll
    for (int i = 0; i < 4; i++) {
        int p = py * 32 + px + i;
        float r[8];
        #pragma unroll
        for (int op = 0; op < 4; op++) {
            ull v = acc2[op][i];
            r[2*op]   = __uint_as_float((unsigned)v);
            r[2*op+1] = __uint_as_float((unsigned)(v >> 32));
        }
        float4 v0, v1;
        v0.x = fmaxf(r[0] + bias[0], 0.0f); v0.y = fmaxf(r[1] + bias[1], 0.0f);
        v0.z = fmaxf(r[2] + bias[2], 0.0f); v0.w = fmaxf(r[3] + bias[3], 0.0f);
        v1.x = fmaxf(r[4] + bias[4], 0.0f); v1.y = fmaxf(r[5] + bias[5], 0.0f);
        v1.z = fmaxf(r[6] + bias[6], 0.0f); v1.w = fmaxf(r[7] + bias[7], 0.0f);
        float* hp = &g_h[(size_t)p * 512 + ob + ot8];
        *(float4*)hp       = v0;
        *(float4*)(hp + 4) = v1;
    }
}

// ---------------- kernel 2: heads, 8 positions per block ----------------
__global__ __launch_bounds__(128) void k_heads(const float* __restrict__ w2, const float* __restrict__ b2,
                                               const float* __restrict__ w3, const float* __restrict__ b3)
{
    __shared__ __align__(16) float hs[8][512];   // 16 KB
    __shared__ float outv[45][8];
    const int pb = blockIdx.x * 8;
    const int tid = threadIdx.x;
    if (tid < 72) g_keep[pb * 9 + tid] = 0;      // reset keep flags for replay

    const float4* src = (const float4*)(g_h + (size_t)pb * 512);
    float4* dst = (float4*)&hs[0][0];
    #pragma unroll
    for (int t = tid; t < 1024; t += 128) dst[t] = src[t];
    __syncthreads();

    const int wrp = tid >> 5, lane = tid & 31;
    for (int o = wrp; o < 45; o += 4) {
        const float* wr; float bb;
        if (o < 9) { wr = w2 + o * 512;       bb = b2[o];     }
        else       { wr = w3 + (o - 9) * 512; bb = b3[o - 9]; }
        float acc[8];
        #pragma unroll
        for (int p = 0; p < 8; p++) acc[p] = 0.0f;
        #pragma unroll 4
        for (int ci = 0; ci < 16; ci++) {
            int c = ci * 32 + lane;
            float wv = wr[c];
            #pragma unroll
            for (int p = 0; p < 8; p++) acc[p] += hs[p][c] * wv;
        }
        #pragma unroll
        for (int p = 0; p < 8; p++) {
            float s = acc[p];
            #pragma unroll
            for (int off = 16; off; off >>= 1) s += __shfl_down_sync(0xffffffffu, s, off);
            if (lane == 0) outv[o][p] = s + bb;
        }
    }
    __syncthreads();

    if (tid < 72) {
        const int pl = tid / 9, a = tid - pl * 9;
        const int p = pb + pl;
        const int y = p >> 5, xx = p & 31;
        float score = 1.0f / (1.0f + expf(-outv[a][pl]));
        float t0 = outv[9 + a*4 + 0][pl], t1 = outv[9 + a*4 + 1][pl];
        float t2 = outv[9 + a*4 + 2][pl], t3 = outv[9 + a*4 + 3][pl];
        float aw = c_aw[a], ah = c_ah[a];
        float acx = (xx + 0.5f) * 16.0f, acy = (y + 0.5f) * 16.0f;
        float cx = acx + t0 * aw, cy = acy + t1 * ah;
        float bw = aw * expf(t2), bh = ah * expf(t3);
        float x1 = cx - bw * 0.5f, y1 = cy - bh * 0.5f;
        float x2 = cx + bw * 0.5f, y2 = cy + bh * 0.5f;
        x1 = fminf(fmaxf(x1, 0.0f), IMGF); y1 = fminf(fmaxf(y1, 0.0f), IMGF);
        x2 = fminf(fmaxf(x2, 0.0f), IMGF); y2 = fminf(fmaxf(y2, 0.0f), IMGF);
        bool valid = (x2 - x1 >= 0.001f) && (y2 - y1 >= 0.001f) && (score >= 0.5f);
        int n = p * 9 + a;
        g_scores[n] = score;
        g_boxes[n] = make_float4(x1, y1, x2, y2);
        ull key;
        if (valid) {
            key = ((ull)__float_as_uint(score) << 32)
                | (ull)(0xFFFFFFFFu - (unsigned)n);
            atomicAdd(&g_M, 1);
        } else {
            key = (ull)(0xFFFFFFFFu - (unsigned)n);
        }
        g_keys[n] = key;
    }
}

// ---------------- kernel 3: exact stable descending argsort ----------------
__global__ __launch_bounds__(256) void k_rank()
{
    __shared__ ull ks[1024];
    const int tid = threadIdx.x;
    const int kl = tid >> 3, sub = tid & 7;
    const int i = blockIdx.x * 32 + kl;
    const ull mykey = g_keys[i];
    int cnt = 0;
    for (int t0 = 0; t0 < NBOX; t0 += 1024) {
        __syncthreads();
        #pragma unroll
        for (int t = tid; t < 1024; t += 256) ks[t] = g_keys[t0 + t];
        __syncthreads();
        #pragma unroll 8
        for (int t = 0; t < 128; t++) cnt += (ks[t * 8 + sub] > mykey) ? 1 : 0;
    }
    cnt += __shfl_down_sync(0xffffffffu, cnt, 4, 8);
    cnt += __shfl_down_sync(0xffffffffu, cnt, 2, 8);
    cnt += __shfl_down_sync(0xffffffffu, cnt, 1, 8);
    if (sub == 0) {
        g_sidx[cnt] = i;
        g_sboxes[cnt] = g_boxes[i];
    }
}

// ---------------- kernel 4: suppression bitmask ----------------
__global__ __launch_bounds__(128) void k_mask()
{
    const int cw = blockIdx.x;
    const int rp = blockIdx.y;
    const int M = g_M;
    if (rp * 128 >= M) return;
    if (cw * 64 >= M) return;
    if (cw < 2 * rp) return;

    __shared__ float4 cb[64];
    __shared__ float  carea[64];
    const int tid = threadIdx.x;
    if (tid < 64) {
        float4 bb = g_sboxes[cw * 64 + tid];
        cb[tid] = bb;
        carea[tid] = (bb.z - bb.x) * (bb.w - bb.y);
    }
    __syncthreads();

    const int r = rp * 128 + tid;
    const int d = r - cw * 64;
    if (r >= M || d > 63) return;

    ull allow = ~0ull;
    if (d >= 0) allow = (d >= 63) ? 0ull : (~0ull << (d + 1));
    int rem = M - cw * 64;
    if (rem < 64) allow &= ((1ull << rem) - 1ull);

    ull word = 0ull;
    if (allow) {
        float4 mb = g_sboxes[r];
        float ma = (mb.z - mb.x) * (mb.w - mb.y);
        unsigned lo = 0, hi = 0;
        #pragma unroll
        for (int jj = 0; jj < 32; jj++) {
            float4 ob = cb[jj];
            float ix1 = fmaxf(mb.x, ob.x), iy1 = fmaxf(mb.y, ob.y);
            float ix2 = fminf(mb.z, ob.z), iy2 = fminf(mb.w, ob.w);
            float inter = fmaxf(ix2 - ix1, 0.0f) * fmaxf(iy2 - iy1, 0.0f);
            float uni = ma + carea[jj] - inter;
            if (inter / fmaxf(uni, 1e-9f) > 0.7f) lo |= (1u << jj);
        }
        #pragma unroll
        for (int jj = 0; jj < 32; jj++) {
            float4 ob = cb[32 + jj];
            float ix1 = fmaxf(mb.x, ob.x), iy1 = fmaxf(mb.y, ob.y);
            float ix2 = fminf(mb.z, ob.z), iy2 = fminf(mb.w, ob.w);
            float inter = fmaxf(ix2 - ix1, 0.0f) * fmaxf(iy2 - iy1, 0.0f);
            float uni = ma + carea[32 + jj] - inter;
            if (inter / fmaxf(uni, 1e-9f) > 0.7f) hi |= (1u << jj);
        }
        word = (((ull)hi << 32) | lo) & allow;
    }
    g_mask[(size_t)r * NW + cw] = word;
}

// ---------------- kernel 5: batched greedy scan, ffs-skip closure ----------------
__global__ __launch_bounds__(128) void k_scan()
{
    __shared__ ull remv[NW];
    __shared__ ull selfw[2][64];        // ping-pong diagonal buffers
    __shared__ ull kb_s;
    const int tid = threadIdx.x;
    const int M = g_M;
    const int nwords = (M + 63) >> 6;
    for (int t = tid; t < NW; t += 128) remv[t] = 0ull;
    if (tid < 64)
        selfw[0][tid] = (tid < M && nwords > 0) ? g_mask[(size_t)tid * NW + 0] : 0ull;
    __syncthreads();

    for (int w = 0; w < nwords; w++) {
        const int rbase = w << 6;
        const int cnt = min(64, M - rbase);
        // prefetch next diagonal into the other buffer (no barrier needed before use;
        // end-of-iteration barrier orders it for the next closure)
        if (tid < 64) {
            int rr2 = rbase + 64 + tid;
            selfw[(w + 1) & 1][tid] = (w + 1 < nwords && rr2 < M)
                ? g_mask[(size_t)rr2 * NW + (w + 1)] : 0ull;
        }
        if (tid == 0) {
            ull supp = remv[w];
            ull full = (cnt < 64) ? ((1ull << cnt) - 1ull) : ~0ull;
            ull avail = ~supp & full;
            ull kb = 0ull;
            const ull* sw = selfw[w & 1];
            while (avail) {
                int rr = __ffsll((long long)avail) - 1;
                kb |= 1ull << rr;
                supp |= sw[rr];
                ull above = (rr >= 63) ? 0ull : (~0ull << (rr + 1));
                avail = ~supp & full & above;
            }
            kb_s = kb;
        }
        __syncthreads();
        const ull kb = kb_s;
        if (tid < cnt && ((kb >> tid) & 1ull))
            g_keep[g_sidx[rbase + tid]] = 1;
        if (kb) {
            for (int w2 = w + 1 + tid; w2 < nwords; w2 += 128) {
                ull accw = remv[w2];
                ull t = kb;
                while (t) {
                    int rr = __ffsll((long long)t) - 1;
                    t &= t - 1ull;
                    accw |= g_mask[(size_t)(rbase + rr) * NW + w2];
                }
                remv[w2] = accw;
            }
        }
        __syncthreads();
    }
}

// ---------------- kernel 6: write output ----------------
__global__ __launch_bounds__(256) void k_out(float* __restrict__ out)
{
    const int n = blockIdx.x * 256 + threadIdx.x;
    float m = g_keep[n] ? 1.0f : 0.0f;
    float4 bx = g_boxes[n];
    float s = g_scores[n];
    float* o = out + (size_t)n * 5;
    o[0] = bx.x * m; o[1] = bx.y * m; o[2] = bx.z * m; o[3] = bx.w * m; o[4] = s * m;
}

// ---------------- launch ----------------
extern "C" void kernel_launch(void* const* d_in, const int* in_sizes, int n_in,
                              void* d_out, int out_size)
{
    const float* fm = (const float*)d_in[0];
    const float* w1 = (const float*)d_in[1];
    const float* b1 = (const float*)d_in[2];
    const float* w2 = (const float*)d_in[3];
    const float* b2 = (const float*)d_in[4];
    const float* w3 = (const float*)d_in[5];
    const float* b3 = (const float*)d_in[6];

    k_conv <<<dim3(8, 16), 128>>>(fm, w1, b1);
    k_heads<<<128, 128>>>(w2, b2, w3, b3);
    k_rank <<<288, 256>>>();
    k_mask <<<dim3(144, 72), 128>>>();
    k_scan <<<1, 128>>>();
    k_out  <<<36, 256>>>((float*)d_out);
}

// round 5
// speedup vs baseline: 1.1618x; 1.1618x over previous
#include <cuda_runtime.h>
#include <cstdint>

typedef unsigned long long ull;

#define FHW 32
#define NA 9
#define NBOX (FHW*FHW*NA)   // 9216
#define NW 144              // mask words per sorted row (9216/64)
#define CIN 256
#define IMGF 512.0f

// ---------------- scratch ----------------
__device__ float  g_h[1024*512];                 // h[pos][och], 2 MB
__device__ float4 g_boxes[NBOX];
__device__ float  g_scores[NBOX];
__device__ ull    g_keys[NBOX];
__device__ int    g_sidx[NBOX];
__device__ float4 g_sboxes[NBOX];
__device__ ull    g_mask[(size_t)NBOX*NW];       // 10.6 MB
__device__ int    g_keep[NBOX];
__device__ int    g_M;

__constant__ float c_aw[9] = {45.254833995939045f, 32.0f, 22.627416997969522f,
                              90.50966799187809f,  64.0f, 45.254833995939045f,
                              181.01933598375618f, 128.0f, 90.50966799187809f};
__constant__ float c_ah[9] = {22.627416997969522f, 32.0f, 45.254833995939045f,
                              45.254833995939045f, 64.0f, 90.50966799187809f,
                              90.50966799187809f,  128.0f, 181.01933598375618f};

// packed dual-fp32 FMA (Blackwell): acc = a*b + acc, per 32-bit lane
#define FMA2(acc, a, b) asm("fma.rn.f32x2 %0, %1, %2, %0;" : "+l"(acc) : "l"(a), "l"(b))

// ---------------- kernel 1: 3x3 conv 256->512 + bias + relu (f32x2) ----------------
__global__ __launch_bounds__(128) void k_conv(const float* __restrict__ x,
                                              const float* __restrict__ w,
                                              const float* __restrict__ b)
{
    __shared__ ull   xs2[16][18][10];     // [c][col][row], value packed {x,x}
    __shared__ float ws[4896];            // [(c*9+tap)*34 + och], stride 34

    const int tid = threadIdx.x;
    const int sx = blockIdx.x & 1, sy = blockIdx.x >> 1;
    const int x0 = sx * 16, y0 = sy * 8;
    const int ob = blockIdx.y * 32;
    const int pt = tid & 31, ot = tid >> 5;
    const int cg = pt & 3, pr = pt >> 2;
    const int cg4 = cg * 4, ot8 = ot * 8;

    if (blockIdx.x == 0 && blockIdx.y == 0 && tid == 0) g_M = 0;

    ull acc2[4][4];
    #pragma unroll
    for (int o = 0; o < 4; o++)
        #pragma unroll
        for (int i = 0; i < 4; i++) acc2[o][i] = 0ull;

    for (int c0 = 0; c0 < CIN; c0 += 16) {
        __syncthreads();
        for (int t = tid; t < 16*18*10; t += 128) {
            int c = t / 180, r2 = t - c*180, col = r2 / 10, row = r2 - col*10;
            int gx = x0 + col - 1, gy = y0 + row - 1;
            float v = 0.0f;
            if ((unsigned)gx < 32u && (unsigned)gy < 32u)
                v = x[(c0 + c) * 1024 + gy * 32 + gx];
            unsigned xb = __float_as_uint(v);
            ull pv; asm("mov.b64 %0, {%1, %1};" : "=l"(pv) : "r"(xb));
            xs2[c][col][row] = pv;
        }
        {
            int o = 0, rr = tid;
            #pragma unroll 4
            for (int k = 0; k < 36; k++) {
                ws[rr * 34 + o] = w[(size_t)(ob + o) * 2304 + c0 * 9 + rr];
                rr += 128; if (rr >= 144) { rr -= 144; o++; }
            }
        }
        __syncthreads();

        for (int c = 0; c < 16; c++) {
            #pragma unroll
            for (int dy = 0; dy < 3; dy++) {
                ull xv[6];
                #pragma unroll
                for (int q = 0; q < 6; q++) xv[q] = xs2[c][cg4 + q][pr + dy];
                #pragma unroll
                for (int dx = 0; dx < 3; dx++) {
                    const ull* wp = (const ull*)&ws[(c*9 + dy*3 + dx) * 34 + ot8];
                    ull w0 = wp[0], w1 = wp[1], w2v = wp[2], w3v = wp[3];
                    #pragma unroll
                    for (int i = 0; i < 4; i++) {
                        ull xp = xv[i + dx];
                        FMA2(acc2[0][i], w0,  xp);
                        FMA2(acc2[1][i], w1,  xp);
                        FMA2(acc2[2][i], w2v, xp);
                        FMA2(acc2[3][i], w3v, xp);
                    }
                }
            }
        }
    }

    float bias[8];
    #pragma unroll
    for (int o = 0; o < 8; o++) bias[o] = b[ob + ot8 + o];

    const int px = x0 + cg4, py = y0 + pr;
    #pragma unroll
    for (int i = 0; i < 4; i++) {
        int p = py * 32 + px + i;
        float r[8];
        #pragma unroll
        for (int op = 0; op < 4; op++) {
            ull v = acc2[op][i];
            r[2*op]   = __uint_as_float((unsigned)v);
            r[2*op+1] = __uint_as_float((unsigned)(v >> 32));
        }
        float4 v0, v1;
        v0.x = fmaxf(r[0] + bias[0], 0.0f); v0.y = fmaxf(r[1] + bias[1], 0.0f);
        v0.z = fmaxf(r[2] + bias[2], 0.0f); v0.w = fmaxf(r[3] + bias[3], 0.0f);
        v1.x = fmaxf(r[4] + bias[4], 0.0f); v1.y = fmaxf(r[5] + bias[5], 0.0f);
        v1.z = fmaxf(r[6] + bias[6], 0.0f); v1.w = fmaxf(r[7] + bias[7], 0.0f);
        float* hp = &g_h[(size_t)p * 512 + ob + ot8];
        *(float4*)hp       = v0;
        *(float4*)(hp + 4) = v1;
    }
}

// ---------------- kernel 2: heads, 4 positions per block (256 blocks) ----------------
__global__ __launch_bounds__(128) void k_heads(const float* __restrict__ w2, const float* __restrict__ b2,
                                               const float* __restrict__ w3, const float* __restrict__ b3)
{
    __shared__ __align__(16) float hs[4][512];   // 8 KB
    __shared__ float outv[45][4];
    const int pb = blockIdx.x * 4;
    const int tid = threadIdx.x;
    if (tid < 36) g_keep[pb * 9 + tid] = 0;      // reset keep flags for replay

    const float4* src = (const float4*)(g_h + (size_t)pb * 512);
    float4* dst = (float4*)&hs[0][0];
    #pragma unroll
    for (int t = tid; t < 512; t += 128) dst[t] = src[t];
    __syncthreads();

    const int wrp = tid >> 5, lane = tid & 31;
    for (int o = wrp; o < 45; o += 4) {
        const float* wr; float bb;
        if (o < 9) { wr = w2 + o * 512;       bb = b2[o];     }
        else       { wr = w3 + (o - 9) * 512; bb = b3[o - 9]; }
        float acc[4];
        #pragma unroll
        for (int p = 0; p < 4; p++) acc[p] = 0.0f;
        #pragma unroll 4
        for (int ci = 0; ci < 16; ci++) {
            int c = ci * 32 + lane;
            float wv = wr[c];
            #pragma unroll
            for (int p = 0; p < 4; p++) acc[p] += hs[p][c] * wv;
        }
        #pragma unroll
        for (int p = 0; p < 4; p++) {
            float s = acc[p];
            #pragma unroll
            for (int off = 16; off; off >>= 1) s += __shfl_down_sync(0xffffffffu, s, off);
            if (lane == 0) outv[o][p] = s + bb;
        }
    }
    __syncthreads();

    if (tid < 36) {
        const int pl = tid / 9, a = tid - pl * 9;
        const int p = pb + pl;
        const int y = p >> 5, xx = p & 31;
        float score = 1.0f / (1.0f + expf(-outv[a][pl]));
        float t0 = outv[9 + a*4 + 0][pl], t1 = outv[9 + a*4 + 1][pl];
        float t2 = outv[9 + a*4 + 2][pl], t3 = outv[9 + a*4 + 3][pl];
        float aw = c_aw[a], ah = c_ah[a];
        float acx = (xx + 0.5f) * 16.0f, acy = (y + 0.5f) * 16.0f;
        float cx = acx + t0 * aw, cy = acy + t1 * ah;
        float bw = aw * expf(t2), bh = ah * expf(t3);
        float x1 = cx - bw * 0.5f, y1 = cy - bh * 0.5f;
        float x2 = cx + bw * 0.5f, y2 = cy + bh * 0.5f;
        x1 = fminf(fmaxf(x1, 0.0f), IMGF); y1 = fminf(fmaxf(y1, 0.0f), IMGF);
        x2 = fminf(fmaxf(x2, 0.0f), IMGF); y2 = fminf(fmaxf(y2, 0.0f), IMGF);
        bool valid = (x2 - x1 >= 0.001f) && (y2 - y1 >= 0.001f) && (score >= 0.5f);
        int n = p * 9 + a;
        g_scores[n] = score;
        g_boxes[n] = make_float4(x1, y1, x2, y2);
        ull key;
        if (valid) {
            key = ((ull)__float_as_uint(score) << 32)
                | (ull)(0xFFFFFFFFu - (unsigned)n);
            atomicAdd(&g_M, 1);
        } else {
            key = (ull)(0xFFFFFFFFu - (unsigned)n);
        }
        g_keys[n] = key;
    }
}

// ---------------- kernel 3: exact stable descending argsort ----------------
__global__ __launch_bounds__(256) void k_rank()
{
    __shared__ ull ks[1024];
    const int tid = threadIdx.x;
    const int kl = tid >> 3, sub = tid & 7;
    const int i = blockIdx.x * 32 + kl;
    const ull mykey = g_keys[i];
    int cnt = 0;
    for (int t0 = 0; t0 < NBOX; t0 += 1024) {
        __syncthreads();
        #pragma unroll
        for (int t = tid; t < 1024; t += 256) ks[t] = g_keys[t0 + t];
        __syncthreads();
        #pragma unroll 8
        for (int t = 0; t < 128; t++) cnt += (ks[t * 8 + sub] > mykey) ? 1 : 0;
    }
    cnt += __shfl_down_sync(0xffffffffu, cnt, 4, 8);
    cnt += __shfl_down_sync(0xffffffffu, cnt, 2, 8);
    cnt += __shfl_down_sync(0xffffffffu, cnt, 1, 8);
    if (sub == 0) {
        g_sidx[cnt] = i;
        g_sboxes[cnt] = g_boxes[i];
    }
}

// ---------------- kernel 4: suppression bitmask ----------------
__global__ __launch_bounds__(128) void k_mask()
{
    const int cw = blockIdx.x;
    const int rp = blockIdx.y;
    const int M = g_M;
    if (rp * 128 >= M) return;
    if (cw * 64 >= M) return;
    if (cw < 2 * rp) return;

    __shared__ float4 cb[64];
    __shared__ float  carea[64];
    const int tid = threadIdx.x;
    if (tid < 64) {
        float4 bb = g_sboxes[cw * 64 + tid];
        cb[tid] = bb;
        carea[tid] = (bb.z - bb.x) * (bb.w - bb.y);
    }
    __syncthreads();

    const int r = rp * 128 + tid;
    const int d = r - cw * 64;
    if (r >= M || d > 63) return;

    ull allow = ~0ull;
    if (d >= 0) allow = (d >= 63) ? 0ull : (~0ull << (d + 1));
    int rem = M - cw * 64;
    if (rem < 64) allow &= ((1ull << rem) - 1ull);

    ull word = 0ull;
    if (allow) {
        float4 mb = g_sboxes[r];
        float ma = (mb.z - mb.x) * (mb.w - mb.y);
        unsigned lo = 0, hi = 0;
        #pragma unroll
        for (int jj = 0; jj < 32; jj++) {
            float4 ob = cb[jj];
            float ix1 = fmaxf(mb.x, ob.x), iy1 = fmaxf(mb.y, ob.y);
            float ix2 = fminf(mb.z, ob.z), iy2 = fminf(mb.w, ob.w);
            float inter = fmaxf(ix2 - ix1, 0.0f) * fmaxf(iy2 - iy1, 0.0f);
            float uni = ma + carea[jj] - inter;
            if (inter / fmaxf(uni, 1e-9f) > 0.7f) lo |= (1u << jj);
        }
        #pragma unroll
        for (int jj = 0; jj < 32; jj++) {
            float4 ob = cb[32 + jj];
            float ix1 = fmaxf(mb.x, ob.x), iy1 = fmaxf(mb.y, ob.y);
            float ix2 = fminf(mb.z, ob.z), iy2 = fminf(mb.w, ob.w);
            float inter = fmaxf(ix2 - ix1, 0.0f) * fmaxf(iy2 - iy1, 0.0f);
            float uni = ma + carea[32 + jj] - inter;
            if (inter / fmaxf(uni, 1e-9f) > 0.7f) hi |= (1u << jj);
        }
        word = (((ull)hi << 32) | lo) & allow;
    }
    g_mask[(size_t)r * NW + cw] = word;
}

// ---------------- kernel 5: batched greedy scan ----------------
// closure: unrolled-64 with STATIC smem addresses (ptxas hoists the LDS).
// tail: counted for-loop over smem kept-list -> MLP>=4 on the L2 loads.
__global__ __launch_bounds__(128) void k_scan()
{
    __shared__ ull remv[NW];
    __shared__ ull selfw[2][64];        // ping-pong diagonal buffers
    __shared__ int krows[64];
    __shared__ ull kb_s;
    const int tid = threadIdx.x;
    const int M = g_M;
    const int nwords = (M + 63) >> 6;
    for (int t = tid; t < NW; t += 128) remv[t] = 0ull;
    if (tid < 64)
        selfw[0][tid] = (tid < M && nwords > 0) ? g_mask[(size_t)tid * NW + 0] : 0ull;
    __syncthreads();

    for (int w = 0; w < nwords; w++) {
        const int rbase = w << 6;
        const int cnt = min(64, M - rbase);
        // prefetch next diagonal into the other buffer
        if (tid < 64) {
            int rr2 = rbase + 64 + tid;
            selfw[(w + 1) & 1][tid] = (w + 1 < nwords && rr2 < M)
                ? g_mask[(size_t)rr2 * NW + (w + 1)] : 0ull;
        }
        if (tid == 0) {
            ull cur = remv[w];
            ull kb = 0ull;
            const ull* sw = selfw[w & 1];
            #pragma unroll
            for (int rr = 0; rr < 64; rr++) {
                ull take = ((cur >> rr) & 1ull) ^ 1ull;
                kb |= take << rr;
                cur |= take ? sw[rr] : 0ull;
            }
            if (cnt < 64) kb &= (1ull << cnt) - 1ull;
            kb_s = kb;
        }
        __syncthreads();
        const ull kb = kb_s;
        const int nk = __popcll(kb);
        // build kept-row list + mark keep flags (parallel, ballot-free via popcount)
        if (tid < cnt && ((kb >> tid) & 1ull)) {
            int pos = __popcll(kb & ((1ull << tid) - 1ull));
            krows[pos] = rbase + tid;
            g_keep[g_sidx[rbase + tid]] = 1;
        }
        __syncthreads();
        if (nk) {
            for (int w2 = w + 1 + tid; w2 < nwords; w2 += 128) {
                ull accw = remv[w2];
                const size_t woff = (size_t)w2;
                #pragma unroll 4
                for (int kk = 0; kk < nk; kk++)
                    accw |= g_mask[(size_t)krows[kk] * NW + woff];
                remv[w2] = accw;
            }
        }
        __syncthreads();
    }
}

// ---------------- kernel 6: write output ----------------
__global__ __launch_bounds__(256) void k_out(float* __restrict__ out)
{
    const int n = blockIdx.x * 256 + threadIdx.x;
    float m = g_keep[n] ? 1.0f : 0.0f;
    float4 bx = g_boxes[n];
    float s = g_scores[n];
    float* o = out + (size_t)n * 5;
    o[0] = bx.x * m; o[1] = bx.y * m; o[2] = bx.z * m; o[3] = bx.w * m; o[4] = s * m;
}

// ---------------- launch ----------------
extern "C" void kernel_launch(void* const* d_in, const int* in_sizes, int n_in,
                              void* d_out, int out_size)
{
    const float* fm = (const float*)d_in[0];
    const float* w1 = (const float*)d_in[1];
    const float* b1 = (const float*)d_in[2];
    const float* w2 = (const float*)d_in[3];
    const float* b2 = (const float*)d_in[4];
    const float* w3 = (const float*)d_in[5];
    const float* b3 = (const float*)d_in[6];

    k_conv <<<dim3(8, 16), 128>>>(fm, w1, b1);
    k_heads<<<256, 128>>>(w2, b2, w3, b3);
    k_rank <<<288, 256>>>();
    k_mask <<<dim3(144, 72), 128>>>();
    k_scan <<<1, 128>>>();
    k_out  <<<36, 256>>>((float*)d_out);
}

// round 6
// speedup vs baseline: 3.7246x; 3.2058x over previous
#include <cuda_runtime.h>
#include <cstdint>

typedef unsigned long long ull;

#define FHW 32
#define NA 9
#define NBOX (FHW*FHW*NA)   // 9216
#define NW 144              // mask words per sorted row (9216/64)
#define CIN 256
#define IMGF 512.0f

// ---------------- scratch ----------------
__device__ float  g_h[1024*512];                 // h[pos][och], 2 MB
__device__ float4 g_boxes[NBOX];
__device__ float  g_scores[NBOX];
__device__ ull    g_keys[NBOX];
__device__ int    g_sidx[NBOX];
__device__ float4 g_sboxes[NBOX];
__device__ ull    g_maskT[(size_t)NW*NBOX];      // TRANSPOSED: [word][row], 10.6 MB
__device__ int    g_keep[NBOX];
__device__ int    g_M;

__constant__ float c_aw[9] = {45.254833995939045f, 32.0f, 22.627416997969522f,
                              90.50966799187809f,  64.0f, 45.254833995939045f,
                              181.01933598375618f, 128.0f, 90.50966799187809f};
__constant__ float c_ah[9] = {22.627416997969522f, 32.0f, 45.254833995939045f,
                              45.254833995939045f, 64.0f, 90.50966799187809f,
                              90.50966799187809f,  128.0f, 181.01933598375618f};

// packed dual-fp32 FMA (Blackwell): acc = a*b + acc, per 32-bit lane
#define FMA2(acc, a, b) asm("fma.rn.f32x2 %0, %1, %2, %0;" : "+l"(acc) : "l"(a), "l"(b))

// ---------------- kernel 1: 3x3 conv 256->512 + bias + relu (f32x2) ----------------
__global__ __launch_bounds__(128) void k_conv(const float* __restrict__ x,
                                              const float* __restrict__ w,
                                              const float* __restrict__ b)
{
    __shared__ ull   xs2[16][18][10];     // [c][col][row], value packed {x,x}
    __shared__ float ws[4896];            // [(c*9+tap)*34 + och], stride 34

    const int tid = threadIdx.x;
    const int sx = blockIdx.x & 1, sy = blockIdx.x >> 1;
    const int x0 = sx * 16, y0 = sy * 8;
    const int ob = blockIdx.y * 32;
    const int pt = tid & 31, ot = tid >> 5;
    const int cg = pt & 3, pr = pt >> 2;
    const int cg4 = cg * 4, ot8 = ot * 8;

    if (blockIdx.x == 0 && blockIdx.y == 0 && tid == 0) g_M = 0;

    ull acc2[4][4];
    #pragma unroll
    for (int o = 0; o < 4; o++)
        #pragma unroll
        for (int i = 0; i < 4; i++) acc2[o][i] = 0ull;

    for (int c0 = 0; c0 < CIN; c0 += 16) {
        __syncthreads();
        for (int t = tid; t < 16*18*10; t += 128) {
            int c = t / 180, r2 = t - c*180, col = r2 / 10, row = r2 - col*10;
            int gx = x0 + col - 1, gy = y0 + row - 1;
            float v = 0.0f;
            if ((unsigned)gx < 32u && (unsigned)gy < 32u)
                v = x[(c0 + c) * 1024 + gy * 32 + gx];
            unsigned xb = __float_as_uint(v);
            ull pv; asm("mov.b64 %0, {%1, %1};" : "=l"(pv) : "r"(xb));
            xs2[c][col][row] = pv;
        }
        {
            int o = 0, rr = tid;
            #pragma unroll 4
            for (int k = 0; k < 36; k++) {
                ws[rr * 34 + o] = w[(size_t)(ob + o) * 2304 + c0 * 9 + rr];
                rr += 128; if (rr >= 144) { rr -= 144; o++; }
            }
        }
        __syncthreads();

        for (int c = 0; c < 16; c++) {
            #pragma unroll
            for (int dy = 0; dy < 3; dy++) {
                ull xv[6];
                #pragma unroll
                for (int q = 0; q < 6; q++) xv[q] = xs2[c][cg4 + q][pr + dy];
                #pragma unroll
                for (int dx = 0; dx < 3; dx++) {
                    const ull* wp = (const ull*)&ws[(c*9 + dy*3 + dx) * 34 + ot8];
                    ull w0 = wp[0], w1 = wp[1], w2v = wp[2], w3v = wp[3];
                    #pragma unroll
                    for (int i = 0; i < 4; i++) {
                        ull xp = xv[i + dx];
                        FMA2(acc2[0][i], w0,  xp);
                        FMA2(acc2[1][i], w1,  xp);
                        FMA2(acc2[2][i], w2v, xp);
                        FMA2(acc2[3][i], w3v, xp);
                    }
                }
            }
        }
    }

    float bias[8];
    #pragma unroll
    for (int o = 0; o < 8; o++) bias[o] = b[ob + ot8 + o];

    const int px = x0 + cg4, py = y0 + pr;
    #pragma unroll
    for (int i = 0; i < 4; i++) {
        int p = py * 32 + px + i;
        float r[8];
        #pragma unroll
        for (int op = 0; op < 4; op++) {
            ull v = acc2[op][i];
            r[2*op]   = __uint_as_float((unsigned)v);
            r[2*op+1] = __uint_as_float((unsigned)(v >> 32));
        }
        float4 v0, v1;
        v0.x = fmaxf(r[0] + bias[0], 0.0f); v0.y = fmaxf(r[1] + bias[1], 0.0f);
        v0.z = fmaxf(r[2] + bias[2], 0.0f); v0.w = fmaxf(r[3] + bias[3], 0.0f);
        v1.x = fmaxf(r[4] + bias[4], 0.0f); v1.y = fmaxf(r[5] + bias[5], 0.0f);
        v1.z = fmaxf(r[6] + bias[6], 0.0f); v1.w = fmaxf(r[7] + bias[7], 0.0f);
        float* hp = &g_h[(size_t)p * 512 + ob + ot8];
        *(float4*)hp       = v0;
        *(float4*)(hp + 4) = v1;
    }
}

// ---------------- kernel 2: heads, 4 positions per block (256 blocks) ----------------
__global__ __launch_bounds__(128) void k_heads(const float* __restrict__ w2, const float* __restrict__ b2,
                                               const float* __restrict__ w3, const float* __restrict__ b3)
{
    __shared__ __align__(16) float hs[4][512];   // 8 KB
    __shared__ float outv[45][4];
    const int pb = blockIdx.x * 4;
    const int tid = threadIdx.x;
    if (tid < 36) g_keep[pb * 9 + tid] = 0;      // reset keep flags for replay

    const float4* src = (const float4*)(g_h + (size_t)pb * 512);
    float4* dst = (float4*)&hs[0][0];
    #pragma unroll
    for (int t = tid; t < 512; t += 128) dst[t] = src[t];
    __syncthreads();

    const int wrp = tid >> 5, lane = tid & 31;
    for (int o = wrp; o < 45; o += 4) {
        const float* wr; float bb;
        if (o < 9) { wr = w2 + o * 512;       bb = b2[o];     }
        else       { wr = w3 + (o - 9) * 512; bb = b3[o - 9]; }
        float acc[4];
        #pragma unroll
        for (int p = 0; p < 4; p++) acc[p] = 0.0f;
        #pragma unroll 4
        for (int ci = 0; ci < 16; ci++) {
            int c = ci * 32 + lane;
            float wv = wr[c];
            #pragma unroll
            for (int p = 0; p < 4; p++) acc[p] += hs[p][c] * wv;
        }
        #pragma unroll
        for (int p = 0; p < 4; p++) {
            float s = acc[p];
            #pragma unroll
            for (int off = 16; off; off >>= 1) s += __shfl_down_sync(0xffffffffu, s, off);
            if (lane == 0) outv[o][p] = s + bb;
        }
    }
    __syncthreads();

    if (tid < 36) {
        const int pl = tid / 9, a = tid - pl * 9;
        const int p = pb + pl;
        const int y = p >> 5, xx = p & 31;
        float score = 1.0f / (1.0f + expf(-outv[a][pl]));
        float t0 = outv[9 + a*4 + 0][pl], t1 = outv[9 + a*4 + 1][pl];
        float t2 = outv[9 + a*4 + 2][pl], t3 = outv[9 + a*4 + 3][pl];
        float aw = c_aw[a], ah = c_ah[a];
        float acx = (xx + 0.5f) * 16.0f, acy = (y + 0.5f) * 16.0f;
        float cx = acx + t0 * aw, cy = acy + t1 * ah;
        float bw = aw * expf(t2), bh = ah * expf(t3);
        float x1 = cx - bw * 0.5f, y1 = cy - bh * 0.5f;
        float x2 = cx + bw * 0.5f, y2 = cy + bh * 0.5f;
        x1 = fminf(fmaxf(x1, 0.0f), IMGF); y1 = fminf(fmaxf(y1, 0.0f), IMGF);
        x2 = fminf(fmaxf(x2, 0.0f), IMGF); y2 = fminf(fmaxf(y2, 0.0f), IMGF);
        bool valid = (x2 - x1 >= 0.001f) && (y2 - y1 >= 0.001f) && (score >= 0.5f);
        int n = p * 9 + a;
        g_scores[n] = score;
        g_boxes[n] = make_float4(x1, y1, x2, y2);
        ull key;
        if (valid) {
            key = ((ull)__float_as_uint(score) << 32)
                | (ull)(0xFFFFFFFFu - (unsigned)n);
            atomicAdd(&g_M, 1);
        } else {
            key = (ull)(0xFFFFFFFFu - (unsigned)n);
        }
        g_keys[n] = key;
    }
}

// ---------------- kernel 3: exact stable descending argsort ----------------
__global__ __launch_bounds__(256) void k_rank()
{
    __shared__ ull ks[1024];
    const int tid = threadIdx.x;
    const int kl = tid >> 3, sub = tid & 7;
    const int i = blockIdx.x * 32 + kl;
    const ull mykey = g_keys[i];
    int cnt = 0;
    for (int t0 = 0; t0 < NBOX; t0 += 1024) {
        __syncthreads();
        #pragma unroll
        for (int t = tid; t < 1024; t += 256) ks[t] = g_keys[t0 + t];
        __syncthreads();
        #pragma unroll 8
        for (int t = 0; t < 128; t++) cnt += (ks[t * 8 + sub] > mykey) ? 1 : 0;
    }
    cnt += __shfl_down_sync(0xffffffffu, cnt, 4, 8);
    cnt += __shfl_down_sync(0xffffffffu, cnt, 2, 8);
    cnt += __shfl_down_sync(0xffffffffu, cnt, 1, 8);
    if (sub == 0) {
        g_sidx[cnt] = i;
        g_sboxes[cnt] = g_boxes[i];
    }
}

// ---------------- kernel 4: suppression bitmask (transposed output) ----------------
__global__ __launch_bounds__(128) void k_mask()
{
    const int cw = blockIdx.x;
    const int rp = blockIdx.y;
    const int M = g_M;
    if (rp * 128 >= M) return;
    if (cw * 64 >= M) return;
    if (cw < 2 * rp) return;

    __shared__ float4 cb[64];
    __shared__ float  carea[64];
    const int tid = threadIdx.x;
    if (tid < 64) {
        float4 bb = g_sboxes[cw * 64 + tid];
        cb[tid] = bb;
        carea[tid] = (bb.z - bb.x) * (bb.w - bb.y);
    }
    __syncthreads();

    const int r = rp * 128 + tid;
    const int d = r - cw * 64;
    if (r >= M || d > 63) return;

    ull allow = ~0ull;
    if (d >= 0) allow = (d >= 63) ? 0ull : (~0ull << (d + 1));
    int rem = M - cw * 64;
    if (rem < 64) allow &= ((1ull << rem) - 1ull);

    ull word = 0ull;
    if (allow) {
        float4 mb = g_sboxes[r];
        float ma = (mb.z - mb.x) * (mb.w - mb.y);
        unsigned lo = 0, hi = 0;
        #pragma unroll
        for (int jj = 0; jj < 32; jj++) {
            float4 ob = cb[jj];
            float ix1 = fmaxf(mb.x, ob.x), iy1 = fmaxf(mb.y, ob.y);
            float ix2 = fminf(mb.z, ob.z), iy2 = fminf(mb.w, ob.w);
            float inter = fmaxf(ix2 - ix1, 0.0f) * fmaxf(iy2 - iy1, 0.0f);
            float uni = ma + carea[jj] - inter;
            if (inter / fmaxf(uni, 1e-9f) > 0.7f) lo |= (1u << jj);
        }
        #pragma unroll
        for (int jj = 0; jj < 32; jj++) {
            float4 ob = cb[32 + jj];
            float ix1 = fmaxf(mb.x, ob.x), iy1 = fmaxf(mb.y, ob.y);
            float ix2 = fminf(mb.z, ob.z), iy2 = fminf(mb.w, ob.w);
            float inter = fmaxf(ix2 - ix1, 0.0f) * fmaxf(iy2 - iy1, 0.0f);
            float uni = ma + carea[32 + jj] - inter;
            if (inter / fmaxf(uni, 1e-9f) > 0.7f) hi |= (1u << jj);
        }
        word = (((ull)hi << 32) | lo) & allow;
    }
    g_maskT[(size_t)cw * NBOX + r] = word;      // coalesced across threads
}

// ---------------- kernel 5: greedy scan, JIT suppression ----------------
// per word w: all 256 threads OR maskT[w][kept rows so far] (full MLP, one L2
// latency exposure) -> reduce -> thread0 runs the 64-step closure -> append
// new kept rows to the running smem list. No eager future-word propagation.
__global__ __launch_bounds__(256) void k_scan()
{
    __shared__ int krows[NBOX];      // all kept rows so far (36 KB)
    __shared__ ull selfw[64];
    __shared__ ull warp_or[8];
    __shared__ ull kb_s;
    __shared__ int kc_s;
    const int tid = threadIdx.x;
    const int lane = tid & 31, wrp = tid >> 5;
    const int M = g_M;
    const int nwords = (M + 63) >> 6;
    if (tid == 0) kc_s = 0;
    if (tid < 8) warp_or[tid] = 0ull;
    __syncthreads();

    for (int w = 0; w < nwords; w++) {
        const int rbase = w << 6;
        const int cnt = min(64, M - rbase);
        const int kc = kc_s;
        const size_t wbase = (size_t)w * NBOX;

        // phase A: JIT suppression OR + diagonal self-mask load (parallel, MLP-rich)
        ull acc = 0ull;
        #pragma unroll 4
        for (int kk = tid; kk < kc; kk += 256)
            acc |= g_maskT[wbase + krows[kk]];
        if (tid < 64)
            selfw[tid] = (tid < cnt) ? g_maskT[wbase + rbase + tid] : 0ull;
        #pragma unroll
        for (int off = 16; off; off >>= 1)
            acc |= __shfl_xor_sync(0xffffffffu, acc, off);
        if (lane == 0) warp_or[wrp] = acc;
        __syncthreads();

        // phase B: sequential closure (thread 0), 4-op dependent chain per row
        if (tid == 0) {
            ull cur = warp_or[0] | warp_or[1] | warp_or[2] | warp_or[3]
                    | warp_or[4] | warp_or[5] | warp_or[6] | warp_or[7];
            ull kb = 0ull;
            #pragma unroll
            for (int rr = 0; rr < 64; rr++) {
                ull bit  = (cur >> rr) & 1ull;
                ull msk  = bit - 1ull;            // ~0 if row kept
                kb  |= msk & (1ull << rr);
                cur |= selfw[rr] & msk;
            }
            if (cnt < 64) kb &= (1ull << cnt) - 1ull;
            kb_s = kb;
        }
        __syncthreads();

        // phase C: append kept rows + mark keep flags
        const ull kb = kb_s;
        if (tid < cnt && ((kb >> tid) & 1ull)) {
            int pos = __popcll(kb & ((1ull << tid) - 1ull));
            krows[kc + pos] = rbase + tid;
            g_keep[g_sidx[rbase + tid]] = 1;
        }
        if (tid == 0) kc_s = kc + __popcll(kb);
        __syncthreads();
    }
}

// ---------------- kernel 6: write output ----------------
__global__ __launch_bounds__(256) void k_out(float* __restrict__ out)
{
    const int n = blockIdx.x * 256 + threadIdx.x;
    float m = g_keep[n] ? 1.0f : 0.0f;
    float4 bx = g_boxes[n];
    float s = g_scores[n];
    float* o = out + (size_t)n * 5;
    o[0] = bx.x * m; o[1] = bx.y * m; o[2] = bx.z * m; o[3] = bx.w * m; o[4] = s * m;
}

// ---------------- launch ----------------
extern "C" void kernel_launch(void* const* d_in, const int* in_sizes, int n_in,
                              void* d_out, int out_size)
{
    const float* fm = (const float*)d_in[0];
    const float* w1 = (const float*)d_in[1];
    const float* b1 = (const float*)d_in[2];
    const float* w2 = (const float*)d_in[3];
    const float* b2 = (const float*)d_in[4];
    const float* w3 = (const float*)d_in[5];
    const float* b3 = (const float*)d_in[6];

    k_conv <<<dim3(8, 16), 128>>>(fm, w1, b1);
    k_heads<<<256, 128>>>(w2, b2, w3, b3);
    k_rank <<<288, 256>>>();
    k_mask <<<dim3(144, 72), 128>>>();
    k_scan <<<1, 256>>>();
    k_out  <<<36, 256>>>((float*)d_out);
}

// round 7
// speedup vs baseline: 4.1724x; 1.1202x over previous
#include <cuda_runtime.h>
#include <cstdint>

typedef unsigned long long ull;

#define FHW 32
#define NA 9
#define NBOX (FHW*FHW*NA)   // 9216
#define NW 144              // mask words per sorted row (9216/64)
#define CIN 256
#define IMGF 512.0f

// ---------------- scratch ----------------
__device__ float  g_h[1024*512];                 // h[pos][och], 2 MB
__device__ float4 g_boxes[NBOX];
__device__ float  g_scores[NBOX];
__device__ ull    g_keys[NBOX];
__device__ int    g_sidx[NBOX];
__device__ float4 g_sboxes[NBOX];
__device__ ull    g_maskT[(size_t)NW*NBOX];      // TRANSPOSED: [word][row], 10.6 MB
__device__ int    g_keep[NBOX];
__device__ int    g_M;

__constant__ float c_aw[9] = {45.254833995939045f, 32.0f, 22.627416997969522f,
                              90.50966799187809f,  64.0f, 45.254833995939045f,
                              181.01933598375618f, 128.0f, 90.50966799187809f};
__constant__ float c_ah[9] = {22.627416997969522f, 32.0f, 45.254833995939045f,
                              45.254833995939045f, 64.0f, 90.50966799187809f,
                              90.50966799187809f,  128.0f, 181.01933598375618f};

// packed dual-fp32 FMA (Blackwell): acc = a*b + acc, per 32-bit lane
#define FMA2(acc, a, b) asm("fma.rn.f32x2 %0, %1, %2, %0;" : "+l"(acc) : "l"(a), "l"(b))

// ---------------- kernel 1: 3x3 conv 256->512 + bias + relu (f32x2) ----------------
// grid (16 spatial tiles of 8x8, 16 och groups), 128 threads.
// thread: 8 och (4 f32x2 pairs) x 2 consecutive x-positions.
__global__ __launch_bounds__(128) void k_conv(const float* __restrict__ x,
                                              const float* __restrict__ w,
                                              const float* __restrict__ b)
{
    __shared__ ull   xs2[16][10][10];     // [c][col][row], value packed {x,x}; 12.5 KB
    __shared__ float ws[4896];            // [(c*9+tap)*34 + och], stride 34

    const int tid = threadIdx.x;
    const int x0 = (blockIdx.x & 3) * 8, y0 = (blockIdx.x >> 2) * 8;
    const int ob = blockIdx.y * 32;
    const int pt = tid & 31, ot = tid >> 5;
    const int cg = pt & 3, pr = pt >> 2;
    const int cg2 = cg * 2, ot8 = ot * 8;

    if (blockIdx.x == 0 && blockIdx.y == 0 && tid == 0) g_M = 0;

    ull acc2[4][2];
    #pragma unroll
    for (int o = 0; o < 4; o++)
        #pragma unroll
        for (int i = 0; i < 2; i++) acc2[o][i] = 0ull;

    for (int c0 = 0; c0 < CIN; c0 += 16) {
        __syncthreads();
        // input patch: 16ch x 10cols x 10rows, duplicated-packed
        for (int t = tid; t < 16*10*10; t += 128) {
            int c = t / 100, r2 = t - c*100, col = r2 / 10, row = r2 - col*10;
            int gx = x0 + col - 1, gy = y0 + row - 1;
            float v = 0.0f;
            if ((unsigned)gx < 32u && (unsigned)gy < 32u)
                v = x[(c0 + c) * 1024 + gy * 32 + gx];
            unsigned xb = __float_as_uint(v);
            ull pv; asm("mov.b64 %0, {%1, %1};" : "=l"(pv) : "r"(xb));
            xs2[c][col][row] = pv;
        }
        {
            int o = 0, rr = tid;
            #pragma unroll 4
            for (int k = 0; k < 36; k++) {
                ws[rr * 34 + o] = w[(size_t)(ob + o) * 2304 + c0 * 9 + rr];
                rr += 128; if (rr >= 144) { rr -= 144; o++; }
            }
        }
        __syncthreads();

        for (int c = 0; c < 16; c++) {
            #pragma unroll
            for (int dy = 0; dy < 3; dy++) {
                ull xv[4];
                #pragma unroll
                for (int q = 0; q < 4; q++) xv[q] = xs2[c][cg2 + q][pr + dy];
                #pragma unroll
                for (int dx = 0; dx < 3; dx++) {
                    const ull* wp = (const ull*)&ws[(c*9 + dy*3 + dx) * 34 + ot8];
                    ull w0 = wp[0], w1 = wp[1], w2v = wp[2], w3v = wp[3];
                    #pragma unroll
                    for (int i = 0; i < 2; i++) {
                        ull xp = xv[i + dx];
                        FMA2(acc2[0][i], w0,  xp);
                        FMA2(acc2[1][i], w1,  xp);
                        FMA2(acc2[2][i], w2v, xp);
                        FMA2(acc2[3][i], w3v, xp);
                    }
                }
            }
        }
    }

    float bias[8];
    #pragma unroll
    for (int o = 0; o < 8; o++) bias[o] = b[ob + ot8 + o];

    const int px = x0 + cg2, py = y0 + pr;
    #pragma unroll
    for (int i = 0; i < 2; i++) {
        int p = py * 32 + px + i;
        float r[8];
        #pragma unroll
        for (int op = 0; op < 4; op++) {
            ull v = acc2[op][i];
            r[2*op]   = __uint_as_float((unsigned)v);
            r[2*op+1] = __uint_as_float((unsigned)(v >> 32));
        }
        float4 v0, v1;
        v0.x = fmaxf(r[0] + bias[0], 0.0f); v0.y = fmaxf(r[1] + bias[1], 0.0f);
        v0.z = fmaxf(r[2] + bias[2], 0.0f); v0.w = fmaxf(r[3] + bias[3], 0.0f);
        v1.x = fmaxf(r[4] + bias[4], 0.0f); v1.y = fmaxf(r[5] + bias[5], 0.0f);
        v1.z = fmaxf(r[6] + bias[6], 0.0f); v1.w = fmaxf(r[7] + bias[7], 0.0f);
        float* hp = &g_h[(size_t)p * 512 + ob + ot8];
        *(float4*)hp       = v0;
        *(float4*)(hp + 4) = v1;
    }
}

// ---------------- kernel 2: heads, 4 positions per block (256 blocks) ----------------
__global__ __launch_bounds__(128) void k_heads(const float* __restrict__ w2, const float* __restrict__ b2,
                                               const float* __restrict__ w3, const float* __restrict__ b3)
{
    __shared__ __align__(16) float hs[4][512];   // 8 KB
    __shared__ float outv[45][4];
    const int pb = blockIdx.x * 4;
    const int tid = threadIdx.x;
    if (tid < 36) g_keep[pb * 9 + tid] = 0;      // reset keep flags for replay

    const float4* src = (const float4*)(g_h + (size_t)pb * 512);
    float4* dst = (float4*)&hs[0][0];
    #pragma unroll
    for (int t = tid; t < 512; t += 128) dst[t] = src[t];
    __syncthreads();

    const int wrp = tid >> 5, lane = tid & 31;
    for (int o = wrp; o < 45; o += 4) {
        const float* wr; float bb;
        if (o < 9) { wr = w2 + o * 512;       bb = b2[o];     }
        else       { wr = w3 + (o - 9) * 512; bb = b3[o - 9]; }
        float acc[4];
        #pragma unroll
        for (int p = 0; p < 4; p++) acc[p] = 0.0f;
        #pragma unroll 4
        for (int ci = 0; ci < 16; ci++) {
            int c = ci * 32 + lane;
            float wv = wr[c];
            #pragma unroll
            for (int p = 0; p < 4; p++) acc[p] += hs[p][c] * wv;
        }
        #pragma unroll
        for (int p = 0; p < 4; p++) {
            float s = acc[p];
            #pragma unroll
            for (int off = 16; off; off >>= 1) s += __shfl_down_sync(0xffffffffu, s, off);
            if (lane == 0) outv[o][p] = s + bb;
        }
    }
    __syncthreads();

    if (tid < 36) {
        const int pl = tid / 9, a = tid - pl * 9;
        const int p = pb + pl;
        const int y = p >> 5, xx = p & 31;
        float score = 1.0f / (1.0f + expf(-outv[a][pl]));
        float t0 = outv[9 + a*4 + 0][pl], t1 = outv[9 + a*4 + 1][pl];
        float t2 = outv[9 + a*4 + 2][pl], t3 = outv[9 + a*4 + 3][pl];
        float aw = c_aw[a], ah = c_ah[a];
        float acx = (xx + 0.5f) * 16.0f, acy = (y + 0.5f) * 16.0f;
        float cx = acx + t0 * aw, cy = acy + t1 * ah;
        float bw = aw * expf(t2), bh = ah * expf(t3);
        float x1 = cx - bw * 0.5f, y1 = cy - bh * 0.5f;
        float x2 = cx + bw * 0.5f, y2 = cy + bh * 0.5f;
        x1 = fminf(fmaxf(x1, 0.0f), IMGF); y1 = fminf(fmaxf(y1, 0.0f), IMGF);
        x2 = fminf(fmaxf(x2, 0.0f), IMGF); y2 = fminf(fmaxf(y2, 0.0f), IMGF);
        bool valid = (x2 - x1 >= 0.001f) && (y2 - y1 >= 0.001f) && (score >= 0.5f);
        int n = p * 9 + a;
        g_scores[n] = score;
        g_boxes[n] = make_float4(x1, y1, x2, y2);
        ull key;
        if (valid) {
            key = ((ull)__float_as_uint(score) << 32)
                | (ull)(0xFFFFFFFFu - (unsigned)n);
            atomicAdd(&g_M, 1);
        } else {
            key = (ull)(0xFFFFFFFFu - (unsigned)n);
        }
        g_keys[n] = key;
    }
}

// ---------------- kernel 3: exact stable descending argsort ----------------
__global__ __launch_bounds__(256) void k_rank()
{
    __shared__ ull ks[1024];
    const int tid = threadIdx.x;
    const int kl = tid >> 3, sub = tid & 7;
    const int i = blockIdx.x * 32 + kl;
    const ull mykey = g_keys[i];
    int cnt = 0;
    for (int t0 = 0; t0 < NBOX; t0 += 1024) {
        __syncthreads();
        #pragma unroll
        for (int t = tid; t < 1024; t += 256) ks[t] = g_keys[t0 + t];
        __syncthreads();
        #pragma unroll 8
        for (int t = 0; t < 128; t++) cnt += (ks[t * 8 + sub] > mykey) ? 1 : 0;
    }
    cnt += __shfl_down_sync(0xffffffffu, cnt, 4, 8);
    cnt += __shfl_down_sync(0xffffffffu, cnt, 2, 8);
    cnt += __shfl_down_sync(0xffffffffu, cnt, 1, 8);
    if (sub == 0) {
        g_sidx[cnt] = i;
        g_sboxes[cnt] = g_boxes[i];
    }
}

// ---------------- kernel 4: suppression bitmask (transposed output) ----------------
__global__ __launch_bounds__(128) void k_mask()
{
    const int cw = blockIdx.x;
    const int rp = blockIdx.y;
    const int M = g_M;
    if (rp * 128 >= M) return;
    if (cw * 64 >= M) return;
    if (cw < 2 * rp) return;

    __shared__ float4 cb[64];
    __shared__ float  carea[64];
    const int tid = threadIdx.x;
    if (tid < 64) {
        float4 bb = g_sboxes[cw * 64 + tid];
        cb[tid] = bb;
        carea[tid] = (bb.z - bb.x) * (bb.w - bb.y);
    }
    __syncthreads();

    const int r = rp * 128 + tid;
    const int d = r - cw * 64;
    if (r >= M || d > 63) return;

    ull allow = ~0ull;
    if (d >= 0) allow = (d >= 63) ? 0ull : (~0ull << (d + 1));
    int rem = M - cw * 64;
    if (rem < 64) allow &= ((1ull << rem) - 1ull);

    ull word = 0ull;
    if (allow) {
        float4 mb = g_sboxes[r];
        float ma = (mb.z - mb.x) * (mb.w - mb.y);
        unsigned lo = 0, hi = 0;
        #pragma unroll
        for (int jj = 0; jj < 32; jj++) {
            float4 ob = cb[jj];
            float ix1 = fmaxf(mb.x, ob.x), iy1 = fmaxf(mb.y, ob.y);
            float ix2 = fminf(mb.z, ob.z), iy2 = fminf(mb.w, ob.w);
            float inter = fmaxf(ix2 - ix1, 0.0f) * fmaxf(iy2 - iy1, 0.0f);
            float uni = ma + carea[jj] - inter;
            if (inter / fmaxf(uni, 1e-9f) > 0.7f) lo |= (1u << jj);
        }
        #pragma unroll
        for (int jj = 0; jj < 32; jj++) {
            float4 ob = cb[32 + jj];
            float ix1 = fmaxf(mb.x, ob.x), iy1 = fmaxf(mb.y, ob.y);
            float ix2 = fminf(mb.z, ob.z), iy2 = fminf(mb.w, ob.w);
            float inter = fmaxf(ix2 - ix1, 0.0f) * fmaxf(iy2 - iy1, 0.0f);
            float uni = ma + carea[32 + jj] - inter;
            if (inter / fmaxf(uni, 1e-9f) > 0.7f) hi |= (1u << jj);
        }
        word = (((ull)hi << 32) | lo) & allow;
    }
    g_maskT[(size_t)cw * NBOX + r] = word;      // coalesced across threads
}

// ---------------- kernel 5: greedy scan, JIT suppression + sparse closure ----------------
// per word w: 256 threads OR maskT[w][kept rows] (full MLP) -> reduce -> thread0
// iterates ONLY over active (self-suppressing) unsuppressed rows via ctz ->
// kb = ~sup & full. selfw is the diagonal block: upper-triangular in-word matrix.
__global__ __launch_bounds__(256) void k_scan()
{
    __shared__ int krows[NBOX];      // kept rows so far (36 KB)
    __shared__ ull selfw[64];
    __shared__ ull warp_or[8];
    __shared__ unsigned act_lo, act_hi;
    __shared__ ull kb_s;
    __shared__ int kc_s;
    const int tid = threadIdx.x;
    const int lane = tid & 31, wrp = tid >> 5;
    const int M = g_M;
    const int nwords = (M + 63) >> 6;
    if (tid == 0) kc_s = 0;
    if (tid < 8) warp_or[tid] = 0ull;
    __syncthreads();

    for (int w = 0; w < nwords; w++) {
        const int rbase = w << 6;
        const int cnt = min(64, M - rbase);
        const int kc = kc_s;
        const size_t wbase = (size_t)w * NBOX;

        // phase A: JIT suppression OR + diagonal self-mask load + active ballot
        ull acc = 0ull;
        #pragma unroll 4
        for (int kk = tid; kk < kc; kk += 256)
            acc |= g_maskT[wbase + krows[kk]];
        ull sw = 0ull;
        if (tid < 64) {
            sw = (tid < cnt) ? g_maskT[wbase + rbase + tid] : 0ull;
            selfw[tid] = sw;
        }
        if (wrp == 0) {
            unsigned bl = __ballot_sync(0xffffffffu, sw != 0ull);
            if (lane == 0) act_lo = bl;
        } else if (wrp == 1) {
            unsigned bl = __ballot_sync(0xffffffffu, sw != 0ull);
            if (lane == 0) act_hi = bl;
        }
        #pragma unroll
        for (int off = 16; off; off >>= 1)
            acc |= __shfl_xor_sync(0xffffffffu, acc, off);
        if (lane == 0) warp_or[wrp] = acc;
        __syncthreads();

        // phase B: sparse closure (thread 0)
        if (tid == 0) {
            ull sup = warp_or[0] | warp_or[1] | warp_or[2] | warp_or[3]
                    | warp_or[4] | warp_or[5] | warp_or[6] | warp_or[7];
            const ull active = ((ull)act_hi << 32) | act_lo;
            const ull full = (cnt < 64) ? ((1ull << cnt) - 1ull) : ~0ull;
            ull act = active & ~sup & full;
            while (act) {
                int rr = __ffsll((long long)act) - 1;
                sup |= selfw[rr];
                ull above = (rr >= 63) ? 0ull : (~0ull << (rr + 1));
                act = active & ~sup & above;
            }
            kb_s = ~sup & full;
        }
        __syncthreads();

        // phase C: append kept rows + mark keep flags
        const ull kb = kb_s;
        if (tid < cnt && ((kb >> tid) & 1ull)) {
            int pos = __popcll(kb & ((1ull << tid) - 1ull));
            krows[kc + pos] = rbase + tid;
            g_keep[g_sidx[rbase + tid]] = 1;
        }
        if (tid == 0) kc_s = kc + __popcll(kb);
        __syncthreads();
    }
}

// ---------------- kernel 6: write output ----------------
__global__ __launch_bounds__(256) void k_out(float* __restrict__ out)
{
    const int n = blockIdx.x * 256 + threadIdx.x;
    float m = g_keep[n] ? 1.0f : 0.0f;
    float4 bx = g_boxes[n];
    float s = g_scores[n];
    float* o = out + (size_t)n * 5;
    o[0] = bx.x * m; o[1] = bx.y * m; o[2] = bx.z * m; o[3] = bx.w * m; o[4] = s * m;
}

// ---------------- launch ----------------
extern "C" void kernel_launch(void* const* d_in, const int* in_sizes, int n_in,
                              void* d_out, int out_size)
{
    const float* fm = (const float*)d_in[0];
    const float* w1 = (const float*)d_in[1];
    const float* b1 = (const float*)d_in[2];
    const float* w2 = (const float*)d_in[3];
    const float* b2 = (const float*)d_in[4];
    const float* w3 = (const float*)d_in[5];
    const float* b3 = (const float*)d_in[6];

    k_conv <<<dim3(16, 16), 128>>>(fm, w1, b1);
    k_heads<<<256, 128>>>(w2, b2, w3, b3);
    k_rank <<<288, 256>>>();
    k_mask <<<dim3(144, 72), 128>>>();
    k_scan <<<1, 256>>>();
    k_out  <<<36, 256>>>((float*)d_out);
}

// round 11
// speedup vs baseline: 4.8755x; 1.1685x over previous
#include <cuda_runtime.h>
#include <cstdint>

typedef unsigned long long ull;

#define FHW 32
#define NA 9
#define NBOX (FHW*FHW*NA)   // 9216
#define NW 144              // mask words per sorted row (9216/64)
#define CIN 256
#define IMGF 512.0f

// ---------------- scratch ----------------
__device__ float  g_h[1024*512];                 // h[pos][och], 2 MB
__device__ float4 g_boxes[NBOX];
__device__ float  g_scores[NBOX];
__device__ ull    g_keys[NBOX];
__device__ int    g_sidx[NBOX];
__device__ float4 g_sboxes[NBOX];
__device__ ull    g_maskT[(size_t)NW*NBOX];      // TRANSPOSED: [word][row], 10.6 MB
__device__ int    g_keep[NBOX];
__device__ int    g_M;

__constant__ float c_aw[9] = {45.254833995939045f, 32.0f, 22.627416997969522f,
                              90.50966799187809f,  64.0f, 45.254833995939045f,
                              181.01933598375618f, 128.0f, 90.50966799187809f};
__constant__ float c_ah[9] = {22.627416997969522f, 32.0f, 45.254833995939045f,
                              45.254833995939045f, 64.0f, 90.50966799187809f,
                              90.50966799187809f,  128.0f, 181.01933598375618f};

// packed dual-fp32 FMA (Blackwell): acc = a*b + acc, per 32-bit lane
#define FMA2(acc, a, b) asm("fma.rn.f32x2 %0, %1, %2, %0;" : "+l"(acc) : "l"(a), "l"(b))

// ---------------- kernel 1: 3x3 conv 256->512 + bias + relu (f32x2) ----------------
__global__ __launch_bounds__(128) void k_conv(const float* __restrict__ x,
                                              const float* __restrict__ w,
                                              const float* __restrict__ b)
{
    __shared__ ull   xs2[16][10][10];     // [c][col][row], value packed {x,x}
    __shared__ float ws[4896];            // [(c*9+tap)*34 + och], stride 34

    const int tid = threadIdx.x;
    const int x0 = (blockIdx.x & 3) * 8, y0 = (blockIdx.x >> 2) * 8;
    const int ob = blockIdx.y * 32;
    const int pt = tid & 31, ot = tid >> 5;
    const int cg = pt & 3, pr = pt >> 2;
    const int cg2 = cg * 2, ot8 = ot * 8;

    if (blockIdx.x == 0 && blockIdx.y == 0 && tid == 0) g_M = 0;

    ull acc2[4][2];
    #pragma unroll
    for (int o = 0; o < 4; o++)
        #pragma unroll
        for (int i = 0; i < 2; i++) acc2[o][i] = 0ull;

    for (int c0 = 0; c0 < CIN; c0 += 16) {
        __syncthreads();
        for (int t = tid; t < 16*10*10; t += 128) {
            int c = t / 100, r2 = t - c*100, col = r2 / 10, row = r2 - col*10;
            int gx = x0 + col - 1, gy = y0 + row - 1;
            float v = 0.0f;
            if ((unsigned)gx < 32u && (unsigned)gy < 32u)
                v = x[(c0 + c) * 1024 + gy * 32 + gx];
            unsigned xb = __float_as_uint(v);
            ull pv; asm("mov.b64 %0, {%1, %1};" : "=l"(pv) : "r"(xb));
            xs2[c][col][row] = pv;
        }
        {
            int o = 0, rr = tid;
            #pragma unroll 4
            for (int k = 0; k < 36; k++) {
                ws[rr * 34 + o] = w[(size_t)(ob + o) * 2304 + c0 * 9 + rr];
                rr += 128; if (rr >= 144) { rr -= 144; o++; }
            }
        }
        __syncthreads();

        for (int c = 0; c < 16; c++) {
            #pragma unroll
            for (int dy = 0; dy < 3; dy++) {
                ull xv[4];
                #pragma unroll
                for (int q = 0; q < 4; q++) xv[q] = xs2[c][cg2 + q][pr + dy];
                #pragma unroll
                for (int dx = 0; dx < 3; dx++) {
                    const ull* wp = (const ull*)&ws[(c*9 + dy*3 + dx) * 34 + ot8];
                    ull w0 = wp[0], w1 = wp[1], w2v = wp[2], w3v = wp[3];
                    #pragma unroll
                    for (int i = 0; i < 2; i++) {
                        ull xp = xv[i + dx];
                        FMA2(acc2[0][i], w0,  xp);
                        FMA2(acc2[1][i], w1,  xp);
                        FMA2(acc2[2][i], w2v, xp);
                        FMA2(acc2[3][i], w3v, xp);
                    }
                }
            }
        }
    }

    float bias[8];
    #pragma unroll
    for (int o = 0; o < 8; o++) bias[o] = b[ob + ot8 + o];

    const int px = x0 + cg2, py = y0 + pr;
    #pragma unroll
    for (int i = 0; i < 2; i++) {
        int p = py * 32 + px + i;
        float r[8];
        #pragma unroll
        for (int op = 0; op < 4; op++) {
            ull v = acc2[op][i];
            r[2*op]   = __uint_as_float((unsigned)v);
            r[2*op+1] = __uint_as_float((unsigned)(v >> 32));
        }
        float4 v0, v1;
        v0.x = fmaxf(r[0] + bias[0], 0.0f); v0.y = fmaxf(r[1] + bias[1], 0.0f);
        v0.z = fmaxf(r[2] + bias[2], 0.0f); v0.w = fmaxf(r[3] + bias[3], 0.0f);
        v1.x = fmaxf(r[4] + bias[4], 0.0f); v1.y = fmaxf(r[5] + bias[5], 0.0f);
        v1.z = fmaxf(r[6] + bias[6], 0.0f); v1.w = fmaxf(r[7] + bias[7], 0.0f);
        float* hp = &g_h[(size_t)p * 512 + ob + ot8];
        *(float4*)hp       = v0;
        *(float4*)(hp + 4) = v1;
    }
}

// ---------------- kernel 2: heads, 4 positions per block (256 blocks) ----------------
__global__ __launch_bounds__(128) void k_heads(const float* __restrict__ w2, const float* __restrict__ b2,
                                               const float* __restrict__ w3, const float* __restrict__ b3)
{
    __shared__ __align__(16) float hs[4][512];
    __shared__ float outv[45][4];
    const int pb = blockIdx.x * 4;
    const int tid = threadIdx.x;
    if (tid < 36) g_keep[pb * 9 + tid] = 0;      // reset keep flags for replay

    const float4* src = (const float4*)(g_h + (size_t)pb * 512);
    float4* dst = (float4*)&hs[0][0];
    #pragma unroll
    for (int t = tid; t < 512; t += 128) dst[t] = src[t];
    __syncthreads();

    const int wrp = tid >> 5, lane = tid & 31;
    for (int o = wrp; o < 45; o += 4) {
        const float* wr; float bb;
        if (o < 9) { wr = w2 + o * 512;       bb = b2[o];     }
        else       { wr = w3 + (o - 9) * 512; bb = b3[o - 9]; }
        float acc[4];
        #pragma unroll
        for (int p = 0; p < 4; p++) acc[p] = 0.0f;
        #pragma unroll 4
        for (int ci = 0; ci < 16; ci++) {
            int c = ci * 32 + lane;
            float wv = wr[c];
            #pragma unroll
            for (int p = 0; p < 4; p++) acc[p] += hs[p][c] * wv;
        }
        #pragma unroll
        for (int p = 0; p < 4; p++) {
            float s = acc[p];
            #pragma unroll
            for (int off = 16; off; off >>= 1) s += __shfl_down_sync(0xffffffffu, s, off);
            if (lane == 0) outv[o][p] = s + bb;
        }
    }
    __syncthreads();

    if (tid < 36) {
        const int pl = tid / 9, a = tid - pl * 9;
        const int p = pb + pl;
        const int y = p >> 5, xx = p & 31;
        float score = 1.0f / (1.0f + expf(-outv[a][pl]));
        float t0 = outv[9 + a*4 + 0][pl], t1 = outv[9 + a*4 + 1][pl];
        float t2 = outv[9 + a*4 + 2][pl], t3 = outv[9 + a*4 + 3][pl];
        float aw = c_aw[a], ah = c_ah[a];
        float acx = (xx + 0.5f) * 16.0f, acy = (y + 0.5f) * 16.0f;
        float cx = acx + t0 * aw, cy = acy + t1 * ah;
        float bw = aw * expf(t2), bh = ah * expf(t3);
        float x1 = cx - bw * 0.5f, y1 = cy - bh * 0.5f;
        float x2 = cx + bw * 0.5f, y2 = cy + bh * 0.5f;
        x1 = fminf(fmaxf(x1, 0.0f), IMGF); y1 = fminf(fmaxf(y1, 0.0f), IMGF);
        x2 = fminf(fmaxf(x2, 0.0f), IMGF); y2 = fminf(fmaxf(y2, 0.0f), IMGF);
        bool valid = (x2 - x1 >= 0.001f) && (y2 - y1 >= 0.001f) && (score >= 0.5f);
        int n = p * 9 + a;
        g_scores[n] = score;
        g_boxes[n] = make_float4(x1, y1, x2, y2);
        ull key;
        if (valid) {
            key = ((ull)__float_as_uint(score) << 32)
                | (ull)(0xFFFFFFFFu - (unsigned)n);
            atomicAdd(&g_M, 1);
        } else {
            key = (ull)(0xFFFFFFFFu - (unsigned)n);
        }
        g_keys[n] = key;
    }
}

// ---------------- kernel 3: exact stable descending argsort ----------------
__global__ __launch_bounds__(256) void k_rank()
{
    __shared__ ull ks[1024];
    const int tid = threadIdx.x;
    const int kl = tid >> 3, sub = tid & 7;
    const int i = blockIdx.x * 32 + kl;
    const ull mykey = g_keys[i];
    int cnt = 0;
    for (int t0 = 0; t0 < NBOX; t0 += 1024) {
        __syncthreads();
        #pragma unroll
        for (int t = tid; t < 1024; t += 256) ks[t] = g_keys[t0 + t];
        __syncthreads();
        #pragma unroll 8
        for (int t = 0; t < 128; t++) cnt += (ks[t * 8 + sub] > mykey) ? 1 : 0;
    }
    cnt += __shfl_down_sync(0xffffffffu, cnt, 4, 8);
    cnt += __shfl_down_sync(0xffffffffu, cnt, 2, 8);
    cnt += __shfl_down_sync(0xffffffffu, cnt, 1, 8);
    if (sub == 0) {
        g_sidx[cnt] = i;
        g_sboxes[cnt] = g_boxes[i];
    }
}

// ---------------- kernel 4: suppression bitmask (transposed, window-compare) ----------------
// exact-equivalent to div.rn(inter,uni) > 0.7f:
//   inter > 0.7000004f*uni  => suppressed;  !(inter > 0.6999996f*uni) => not;
//   else (ambiguous, ~1e-6 of pairs) resolve with the original exact division.
__global__ __launch_bounds__(128) void k_mask()
{
    const int cw = blockIdx.x;
    const int rp = blockIdx.y;
    const int M = g_M;
    if (rp * 128 >= M) return;
    if (cw * 64 >= M) return;
    if (cw < 2 * rp) return;

    __shared__ float4 cb[64];
    __shared__ float  carea[64];
    const int tid = threadIdx.x;
    if (tid < 64) {
        float4 bb = g_sboxes[cw * 64 + tid];
        cb[tid] = bb;
        carea[tid] = (bb.z - bb.x) * (bb.w - bb.y);
    }
    __syncthreads();

    const int r = rp * 128 + tid;
    const int d = r - cw * 64;
    if (r >= M || d > 63) return;

    ull allow = ~0ull;
    if (d >= 0) allow = (d >= 63) ? 0ull : (~0ull << (d + 1));
    int rem = M - cw * 64;
    if (rem < 64) allow &= ((1ull << rem) - 1ull);

    ull word = 0ull;
    if (allow) {
        float4 mb = g_sboxes[r];
        float ma = (mb.z - mb.x) * (mb.w - mb.y);
        unsigned bits[2] = {0u, 0u};
        unsigned amb[2]  = {0u, 0u};
        #pragma unroll
        for (int half = 0; half < 2; half++) {
            #pragma unroll
            for (int jj = 0; jj < 32; jj++) {
                int j = half * 32 + jj;
                float4 ob = cb[j];
                float ix1 = fmaxf(mb.x, ob.x), iy1 = fmaxf(mb.y, ob.y);
                float ix2 = fminf(mb.z, ob.z), iy2 = fminf(mb.w, ob.w);
                float inter = fmaxf(ix2 - ix1, 0.0f) * fmaxf(iy2 - iy1, 0.0f);
                float uni = ma + carea[j] - inter;
                bool h = inter > 0.7000004f * uni;
                bool l = inter > 0.6999996f * uni;
                bits[half] |= ((unsigned)h) << jj;
                amb[half]  |= ((unsigned)(h != l)) << jj;
            }
        }
        // resolve rare ambiguous pairs with exact division
        #pragma unroll
        for (int half = 0; half < 2; half++) {
            unsigned a = amb[half];
            while (a) {
                int jj = __ffs(a) - 1; a &= a - 1;
                int j = half * 32 + jj;
                float4 ob = cb[j];
                float ix1 = fmaxf(mb.x, ob.x), iy1 = fmaxf(mb.y, ob.y);
                float ix2 = fminf(mb.z, ob.z), iy2 = fminf(mb.w, ob.w);
                float inter = fmaxf(ix2 - ix1, 0.0f) * fmaxf(iy2 - iy1, 0.0f);
                float uni = ma + carea[j] - inter;
                bool s = (inter / fmaxf(uni, 1e-9f)) > 0.7f;
                bits[half] = (bits[half] & ~(1u << jj)) | (((unsigned)s) << jj);
            }
        }
        word = (((ull)bits[1] << 32) | bits[0]) & allow;
    }
    g_maskT[(size_t)cw * NBOX + r] = word;      // coalesced across threads
}

// ---------------- kernel 5: greedy scan, pipelined JIT suppression ----------------
// iteration w consumes regs prefetched during w-1 (accR/specR/swR for word w),
// so the L2 latency of every load is hidden behind the previous word's
// closure + barriers. specR covers rows kept at word w-1 (selected by kbPrev).
__global__ __launch_bounds__(256) void k_scan()
{
    __shared__ int krows[NBOX];      // kept rows so far
    __shared__ ull selfw[64];
    __shared__ ull warp_or[8];
    __shared__ unsigned act_lo, act_hi;
    __shared__ ull kb_s;
    __shared__ int kc_s;
    const int tid = threadIdx.x;
    const int lane = tid & 31, wrp = tid >> 5;
    const int M = g_M;
    const int nwords = (M + 63) >> 6;
    if (tid == 0) { kc_s = 0; }
    if (tid < 8) warp_or[tid] = 0ull;
    __syncthreads();

    // prologue: prefetch word 0's diagonal
    ull accR = 0ull, specR = 0ull, swR = 0ull;
    if (nwords > 0 && tid < 64)
        swR = (tid < M) ? g_maskT[(size_t)0 * NBOX + tid] : 0ull;
    ull kbPrev = 0ull;

    for (int w = 0; w < nwords; w++) {
        const int rbase = w << 6;
        const int cnt = min(64, M - rbase);
        const int kc = kc_s;

        // prefetch word w+1 (issued first; independent of this word's phases)
        ull accN = 0ull, specN = 0ull, swN = 0ull;
        if (w + 1 < nwords) {
            const size_t nb = (size_t)(w + 1) * NBOX;
            #pragma unroll 4
            for (int kk = tid; kk < kc; kk += 256)
                accN |= g_maskT[nb + krows[kk]];
            if (tid < 64) {
                specN = (rbase + tid < M)      ? g_maskT[nb + rbase + tid]      : 0ull;
                swN   = (rbase + 64 + tid < M) ? g_maskT[nb + rbase + 64 + tid] : 0ull;
            }
        }

        // phase A: combine prefetched acc + prev-word kept contributions + diag
        ull contrib = accR;
        if (tid < 64) {
            if ((kbPrev >> tid) & 1ull) contrib |= specR;
            selfw[tid] = swR;
        }
        if (wrp == 0) {
            unsigned bl = __ballot_sync(0xffffffffu, swR != 0ull);
            if (lane == 0) act_lo = bl;
        } else if (wrp == 1) {
            unsigned bl = __ballot_sync(0xffffffffu, swR != 0ull);
            if (lane == 0) act_hi = bl;
        }
        #pragma unroll
        for (int off = 16; off; off >>= 1)
            contrib |= __shfl_xor_sync(0xffffffffu, contrib, off);
        if (lane == 0) warp_or[wrp] = contrib;
        __syncthreads();

        // phase B: sparse closure (thread 0)
        if (tid == 0) {
            ull sup = warp_or[0] | warp_or[1] | warp_or[2] | warp_or[3]
                    | warp_or[4] | warp_or[5] | warp_or[6] | warp_or[7];
            const ull active = ((ull)act_hi << 32) | act_lo;
            const ull full = (cnt < 64) ? ((1ull << cnt) - 1ull) : ~0ull;
            ull act = active & ~sup & full;
            while (act) {
                int rr = __ffsll((long long)act) - 1;
                sup |= selfw[rr];
                ull above = (rr >= 63) ? 0ull : (~0ull << (rr + 1));
                act = active & ~sup & above;
            }
            kb_s = ~sup & full;
        }
        __syncthreads();

        // phase C: append kept rows + mark keep flags
        const ull kb = kb_s;
        if (tid < cnt && ((kb >> tid) & 1ull)) {
            int pos = __popcll(kb & ((1ull << tid) - 1ull));
            krows[kc + pos] = rbase + tid;
            g_keep[g_sidx[rbase + tid]] = 1;
        }
        if (tid == 0) kc_s = kc + __popcll(kb);
        kbPrev = kb;
        accR = accN; specR = specN; swR = swN;
        __syncthreads();
    }
}

// ---------------- kernel 6: write output ----------------
__global__ __launch_bounds__(256) void k_out(float* __restrict__ out)
{
    const int n = blockIdx.x * 256 + threadIdx.x;
    float m = g_keep[n] ? 1.0f : 0.0f;
    float4 bx = g_boxes[n];
    float s = g_scores[n];
    float* o = out + (size_t)n * 5;
    o[0] = bx.x * m; o[1] = bx.y * m; o[2] = bx.z * m; o[3] = bx.w * m; o[4] = s * m;
}

// ---------------- launch ----------------
extern "C" void kernel_launch(void* const* d_in, const int* in_sizes, int n_in,
                              void* d_out, int out_size)
{
    const float* fm = (const float*)d_in[0];
    const float* w1 = (const float*)d_in[1];
    const float* b1 = (const float*)d_in[2];
    const float* w2 = (const float*)d_in[3];
    const float* b2 = (const float*)d_in[4];
    const float* w3 = (const float*)d_in[5];
    const float* b3 = (const float*)d_in[6];

    k_conv <<<dim3(16, 16), 128>>>(fm, w1, b1);
    k_heads<<<256, 128>>>(w2, b2, w3, b3);
    k_rank <<<288, 256>>>();
    k_mask <<<dim3(144, 72), 128>>>();
    k_scan <<<1, 256>>>();
    k_out  <<<36, 256>>>((float*)d_out);
}